// round 12
// baseline (speedup 1.0000x reference)
#include <cuda_runtime.h>
#include <math.h>

#define HH 80
#define WW 80
#define CI 256
#define NF 128
#define NPIX (HH*WW)   // 6400
#define BATCH 2

// Scratch (device globals; no allocations allowed)
__device__ float g_qkv[3][BATCH][NPIX*NF];   // theta, phi(flat), g
__device__ float g_att[BATCH][NPIX*NF];      // attention output (n, c)

// ---------------- packed f32x2 helpers (FFMA2 via PTX) ----------------------
typedef unsigned long long ull;

__device__ __forceinline__ ull pack2(float lo, float hi) {
    ull r; asm("mov.b64 %0, {%1, %2};" : "=l"(r) : "f"(lo), "f"(hi)); return r;
}
__device__ __forceinline__ ull dup2(float v) { return pack2(v, v); }
__device__ __forceinline__ void fma2(ull& d, ull a, ull b) {
    asm("fma.rn.f32x2 %0, %1, %2, %3;" : "=l"(d) : "l"(a), "l"(b), "l"(d));
}
__device__ __forceinline__ ull mul2(ull a, ull b) {
    ull r; asm("mul.rn.f32x2 %0, %1, %2;" : "=l"(r) : "l"(a), "l"(b)); return r;
}
__device__ __forceinline__ float2 unpk(ull v) {
    float2 f; asm("mov.b64 {%0, %1}, %2;" : "=f"(f.x), "=f"(f.y) : "l"(v)); return f;
}

// ---------------------------------------------------------------------------
// Conv 3x3 SAME, CIN=256 -> CO=128 (theta/phi/g).
// Tile: 8 rows x 8 px x 128 co. Block 256 threads.
// Thread: co-quad c4=4*(t&31), row r=t>>5 (0..7), 8 px.
// ci split into two 128-channel phases -> smem 60KB -> 3 CTAs/SM.
// Per ci: 48 FFMA2 + 10 dup + 3 LDS + 3 LDG.128 (fma ceiling ~71%).
// ---------------------------------------------------------------------------
#define PADC 12
#define CIH 128
__global__ __launch_bounds__(256) void conv_qkv_kernel(
    const float* __restrict__ x,
    const float* __restrict__ w0,
    const float* __restrict__ w1,
    const float* __restrict__ w2)
{
    extern __shared__ float s_in[];            // [10][CIH][PADC] (10 cols used)
    const int x0 = blockIdx.x * 8;
    const int y0 = blockIdx.y * 8;
    const int b  = blockIdx.z / 3;
    const int cv = blockIdx.z % 3;
    const float* __restrict__ wgt = (cv == 0) ? w0 : ((cv == 1) ? w1 : w2);
    float* __restrict__ outp = g_qkv[cv][b];
    const int t = threadIdx.x;

    const int c4 = (t & 31) * 4;
    const int r  = t >> 5;     // 0..7

    ull acc[8][2];
#pragma unroll
    for (int p = 0; p < 8; p++) { acc[p][0] = dup2(0.f); acc[p][1] = dup2(0.f); }

    const int kstride = CI * NF;   // weight offset per kx

#pragma unroll 1
    for (int phase = 0; phase < 2; phase++) {
        const int cibase = phase * CIH;
        if (phase) __syncthreads();
        // Patch: rows y0-1 .. y0+8, px x0-1 .. x0+8, channels cibase..+127
        for (int i = t; i < 10 * 10 * CIH; i += 256) {
            int ci = i & (CIH - 1);
            int xi = (i >> 7) % 10;
            int rr = i / (10 * CIH);
            int gy = y0 - 1 + rr, gx = x0 - 1 + xi;
            float v = 0.f;
            if (gy >= 0 && gy < HH && gx >= 0 && gx < WW)
                v = x[((b * HH + gy) * WW + gx) * CI + cibase + ci];
            s_in[(rr * CIH + ci) * PADC + xi] = v;
        }
        __syncthreads();

        for (int ky = 0; ky < 3; ky++) {
            const float* srow0 = &s_in[((r + ky) * CIH) * PADC];
            const float* wbase = &wgt[(ky * 3 * CI + cibase) * NF + c4];
            ulonglong2 n0 = *(const ulonglong2*)&wbase[0];
            ulonglong2 n1 = *(const ulonglong2*)&wbase[kstride];
            ulonglong2 n2 = *(const ulonglong2*)&wbase[2 * kstride];
#pragma unroll 1
            for (int ci = 0; ci < CIH; ci++) {
                ulonglong2 u0 = n0, u1 = n1, u2 = n2;
                if (ci + 1 < CIH) {
                    const float* wn = wbase + (ci + 1) * NF;
                    n0 = *(const ulonglong2*)&wn[0];
                    n1 = *(const ulonglong2*)&wn[kstride];
                    n2 = *(const ulonglong2*)&wn[2 * kstride];
                }
                const float* row = srow0 + ci * PADC;
                float4 wA = *(const float4*)&row[0];
                float4 wB = *(const float4*)&row[4];
                float2 wE = *(const float2*)&row[8];
                ull wd[10];
                wd[0]=dup2(wA.x); wd[1]=dup2(wA.y); wd[2]=dup2(wA.z); wd[3]=dup2(wA.w);
                wd[4]=dup2(wB.x); wd[5]=dup2(wB.y); wd[6]=dup2(wB.z); wd[7]=dup2(wB.w);
                wd[8]=dup2(wE.x); wd[9]=dup2(wE.y);
#pragma unroll
                for (int p = 0; p < 8; p++) {
                    fma2(acc[p][0], wd[p],     u0.x);
                    fma2(acc[p][1], wd[p],     u0.y);
                    fma2(acc[p][0], wd[p + 1], u1.x);
                    fma2(acc[p][1], wd[p + 1], u1.y);
                    fma2(acc[p][0], wd[p + 2], u2.x);
                    fma2(acc[p][1], wd[p + 2], u2.y);
                }
            }
        }
    }
    const int nbase = (y0 + r) * WW + x0;
#pragma unroll
    for (int p = 0; p < 8; p++) {
        float2 v0 = unpk(acc[p][0]);
        float2 v1 = unpk(acc[p][1]);
        *(float4*)&outp[(nbase + p) * NF + c4] = make_float4(v0.x, v0.y, v1.x, v1.y);
    }
}

// ---------------------------------------------------------------------------
// Flash attention (R8 measured-best): 256 threads, frag 6x8, packed f32x2,
// QROWS=96 -> 134 CTAs, float4 P-reads, c-unroll x2.
// ---------------------------------------------------------------------------
#define LD  132
#define LDQ 100
#define QROWS 96
#define SM_Q 0
#define SM_B (128*LDQ)
#define SM_G (128*LDQ + 128*LD)

__global__ __launch_bounds__(256, 1) void flash_kernel()
{
    extern __shared__ float sm[];
    float* Qst = sm + SM_Q;   // [c][i] transposed, i < 96
    float* Bs  = sm + SM_B;   // K-chunk, then reused as P
    float* Gs  = sm + SM_G;

    const int b  = blockIdx.y;
    const int q0 = blockIdx.x * QROWS;
    const float* __restrict__ theta = g_qkv[0][b];
    const float* __restrict__ phi   = g_qkv[1][b];
    const float* __restrict__ gmat  = g_qkv[2][b];

    const int t  = threadIdx.x;
    const int tx = t & 15, ty = t >> 4;
    const int i0 = ty * 6, j0 = tx * 8;

    for (int idx = t; idx < QROWS * 128; idx += 256) {
        int i = idx >> 7, c = idx & 127;
        int qi = q0 + i; if (qi >= NPIX) qi = NPIX - 1;
        Qst[c * LDQ + i] = theta[qi * NF + c];
    }

    ull o2[6][4];
    float mrun[6], lrun[6];
#pragma unroll
    for (int ii = 0; ii < 6; ii++) {
        mrun[ii] = -1e30f; lrun[ii] = 0.f;
#pragma unroll
        for (int cp = 0; cp < 4; cp++) o2[ii][cp] = dup2(0.f);
    }
    __syncthreads();

    for (int km = 0; km < 50; km++) {
        const int m0 = km * 128;
        for (int idx = t; idx < 4096; idx += 256) {
            int rr = idx >> 5;
            int cc = (idx & 31) << 2;
            *(float4*)&Bs[rr * LD + cc] = *(const float4*)&phi[rr * NPIX + m0 + cc];
            *(float4*)&Gs[rr * LD + cc] = *(const float4*)&gmat[(m0 + rr) * NF + cc];
        }
        __syncthreads();

        ull s2[6][4];
#pragma unroll
        for (int ii = 0; ii < 6; ii++)
#pragma unroll
            for (int jp = 0; jp < 4; jp++) s2[ii][jp] = dup2(0.f);

#pragma unroll 1
        for (int c = 0; c < 128; c += 2) {
#pragma unroll
            for (int cc2 = 0; cc2 < 2; cc2++) {
                const float* qrow = &Qst[(c + cc2) * LDQ + i0];
                float2 a01 = *(const float2*)&qrow[0];
                float2 a23 = *(const float2*)&qrow[2];
                float2 a45 = *(const float2*)&qrow[4];
                ull av[6] = {dup2(a01.x), dup2(a01.y), dup2(a23.x),
                             dup2(a23.y), dup2(a45.x), dup2(a45.y)};
                const ulonglong2* brow = (const ulonglong2*)&Bs[(c + cc2) * LD + j0];
                ulonglong2 b01 = brow[0], b23 = brow[1];
                ull bv[4] = {b01.x, b01.y, b23.x, b23.y};
#pragma unroll
                for (int ii = 0; ii < 6; ii++)
#pragma unroll
                    for (int jp = 0; jp < 4; jp++)
                        fma2(s2[ii][jp], av[ii], bv[jp]);
            }
        }
        __syncthreads();

#pragma unroll
        for (int ii = 0; ii < 6; ii++) {
            float sv[8];
            float2 u;
            u = unpk(s2[ii][0]); sv[0] = u.x; sv[1] = u.y;
            u = unpk(s2[ii][1]); sv[2] = u.x; sv[3] = u.y;
            u = unpk(s2[ii][2]); sv[4] = u.x; sv[5] = u.y;
            u = unpk(s2[ii][3]); sv[6] = u.x; sv[7] = u.y;
            float mx = sv[0];
#pragma unroll
            for (int jj = 1; jj < 8; jj++) mx = fmaxf(mx, sv[jj]);
            mx = fmaxf(mx, __shfl_xor_sync(0xffffffffu, mx, 1));
            mx = fmaxf(mx, __shfl_xor_sync(0xffffffffu, mx, 2));
            mx = fmaxf(mx, __shfl_xor_sync(0xffffffffu, mx, 4));
            mx = fmaxf(mx, __shfl_xor_sync(0xffffffffu, mx, 8));
            float mnew = fmaxf(mrun[ii], mx);
            float f = __expf(mrun[ii] - mnew);
            mrun[ii] = mnew;
            float sum = 0.f;
#pragma unroll
            for (int jj = 0; jj < 8; jj++) {
                float p = __expf(sv[jj] - mnew);
                sv[jj] = p;
                sum += p;
            }
            sum += __shfl_xor_sync(0xffffffffu, sum, 1);
            sum += __shfl_xor_sync(0xffffffffu, sum, 2);
            sum += __shfl_xor_sync(0xffffffffu, sum, 4);
            sum += __shfl_xor_sync(0xffffffffu, sum, 8);
            lrun[ii] = lrun[ii] * f + sum;
            ull f2v = dup2(f);
#pragma unroll
            for (int cp = 0; cp < 4; cp++)
                o2[ii][cp] = mul2(o2[ii][cp], f2v);
            *(float4*)&Bs[(i0 + ii) * LD + j0]     = make_float4(sv[0], sv[1], sv[2], sv[3]);
            *(float4*)&Bs[(i0 + ii) * LD + j0 + 4] = make_float4(sv[4], sv[5], sv[6], sv[7]);
        }
        __syncthreads();

#pragma unroll 1
        for (int j4 = 0; j4 < 128; j4 += 4) {
            float4 pv4[6];
#pragma unroll
            for (int ii = 0; ii < 6; ii++)
                pv4[ii] = *(const float4*)&Bs[(i0 + ii) * LD + j4];
#pragma unroll
            for (int jj = 0; jj < 4; jj++) {
                const ulonglong2* grow = (const ulonglong2*)&Gs[(j4 + jj) * LD + j0];
                ulonglong2 g01 = grow[0], g23 = grow[1];
                ull gv[4] = {g01.x, g01.y, g23.x, g23.y};
#pragma unroll
                for (int ii = 0; ii < 6; ii++) {
                    float pj = (jj == 0) ? pv4[ii].x : (jj == 1) ? pv4[ii].y
                             : (jj == 2) ? pv4[ii].z : pv4[ii].w;
                    ull pv = dup2(pj);
#pragma unroll
                    for (int cp = 0; cp < 4; cp++)
                        fma2(o2[ii][cp], pv, gv[cp]);
                }
            }
        }
        __syncthreads();
    }

#pragma unroll
    for (int ii = 0; ii < 6; ii++) {
        int row = q0 + i0 + ii;
        if (row >= NPIX) continue;
        float inv = 1.f / lrun[ii];
        float2 v0 = unpk(o2[ii][0]), v1 = unpk(o2[ii][1]);
        float2 v2 = unpk(o2[ii][2]), v3 = unpk(o2[ii][3]);
        float* dst = &g_att[b][row * NF + j0];
        *(float4*)&dst[0] = make_float4(v0.x * inv, v0.y * inv, v1.x * inv, v1.y * inv);
        *(float4*)&dst[4] = make_float4(v2.x * inv, v2.y * inv, v3.x * inv, v3.y * inv);
    }
}

// ---------------------------------------------------------------------------
// Final conv 3x3, 128 -> 256, + residual add, writes d_out. (R8 exact)
// Tile: 2 rows x 16 px x 256 co. Block 512 threads.
// ---------------------------------------------------------------------------
#define PADF 20
__global__ __launch_bounds__(512) void conv_final_kernel(
    const float* __restrict__ x,
    const float* __restrict__ wc,
    float* __restrict__ out)
{
    extern __shared__ float s_in[];            // [4][NF][PADF]
    const int x0 = blockIdx.x * 16;
    const int y0 = blockIdx.y * 2;
    const int b  = blockIdx.z;
    const int t  = threadIdx.x;
    const float* __restrict__ ain = g_att[b];

    for (int i = t; i < 4 * 18 * NF; i += 512) {
        int ci = i & (NF - 1);
        int xi = (i >> 7) % 18;
        int r  = i / (18 * NF);
        int gy = y0 - 1 + r, gx = x0 - 1 + xi;
        float v = 0.f;
        if (gy >= 0 && gy < HH && gx >= 0 && gx < WW)
            v = ain[(gy * WW + gx) * NF + ci];
        s_in[(r * NF + ci) * PADF + xi] = v;
    }
    __syncthreads();

    const int c2  = (t & 127) * 2;
    const int pxb = ((t >> 7) & 1) * 8;
    const int r   = t >> 8;

    ull acc[8];
#pragma unroll
    for (int p = 0; p < 8; p++) acc[p] = dup2(0.f);

    const int kstride = NF * CI;

    for (int ky = 0; ky < 3; ky++) {
        const float* srow0 = &s_in[((r + ky) * NF) * PADF + pxb];
        const float* wbase = &wc[(ky * 3 * NF) * CI + c2];
        ull a0 = *(const ull*)&wbase[0];
        ull a1 = *(const ull*)&wbase[kstride];
        ull a2 = *(const ull*)&wbase[2 * kstride];
        ull e0 = *(const ull*)&wbase[CI];
        ull e1 = *(const ull*)&wbase[kstride + CI];
        ull e2 = *(const ull*)&wbase[2 * kstride + CI];
#pragma unroll 1
        for (int ci = 0; ci < NF; ci += 2) {
            ull u0 = a0, u1 = a1, u2 = a2;
            ull v0 = e0, v1 = e1, v2 = e2;
            if (ci + 2 < NF) {
                const float* wn = wbase + (ci + 2) * CI;
                a0 = *(const ull*)&wn[0];
                a1 = *(const ull*)&wn[kstride];
                a2 = *(const ull*)&wn[2 * kstride];
                e0 = *(const ull*)&wn[CI];
                e1 = *(const ull*)&wn[kstride + CI];
                e2 = *(const ull*)&wn[2 * kstride + CI];
            }
#pragma unroll
            for (int half = 0; half < 2; half++) {
                const float* row = srow0 + (ci + half) * PADF;
                float4 wA = *(const float4*)&row[0];
                float4 wB = *(const float4*)&row[4];
                float2 wE = *(const float2*)&row[8];
                ull wd[10];
                wd[0]=dup2(wA.x); wd[1]=dup2(wA.y); wd[2]=dup2(wA.z); wd[3]=dup2(wA.w);
                wd[4]=dup2(wB.x); wd[5]=dup2(wB.y); wd[6]=dup2(wB.z); wd[7]=dup2(wB.w);
                wd[8]=dup2(wE.x); wd[9]=dup2(wE.y);
                ull wv0 = half ? v0 : u0;
                ull wv1 = half ? v1 : u1;
                ull wv2 = half ? v2 : u2;
#pragma unroll
                for (int p = 0; p < 8; p++) {
                    fma2(acc[p], wd[p],     wv0);
                    fma2(acc[p], wd[p + 1], wv1);
                    fma2(acc[p], wd[p + 2], wv2);
                }
            }
        }
    }
#pragma unroll
    for (int p = 0; p < 8; p++) {
        float2 v = unpk(acc[p]);
        int gi = ((b * HH + y0 + r) * WW + x0 + pxb + p) * CI + c2;
        float2 xv = *(const float2*)&x[gi];
        *(float2*)&out[gi] = make_float2(xv.x + v.x, xv.y + v.y);
    }
}

// ---------------------------------------------------------------------------
extern "C" void kernel_launch(void* const* d_in, const int* in_sizes, int n_in,
                              void* d_out, int out_size)
{
    const float* x  = (const float*)d_in[0];
    const float* wt = (const float*)d_in[1];
    const float* wp = (const float*)d_in[2];
    const float* wg = (const float*)d_in[3];
    const float* wc = (const float*)d_in[4];
    float* out = (float*)d_out;

    const int smem_qkv   = 10 * CIH * PADC * 4;               // 61440
    const int smem_flash = (128 * LDQ + 2 * 128 * LD) * 4;    // 186368
    const int smem_final = 4 * NF * PADF * 4;                 // 40960

    cudaFuncSetAttribute(conv_qkv_kernel,   cudaFuncAttributeMaxDynamicSharedMemorySize, smem_qkv);
    cudaFuncSetAttribute(flash_kernel,      cudaFuncAttributeMaxDynamicSharedMemorySize, smem_flash);
    cudaFuncSetAttribute(conv_final_kernel, cudaFuncAttributeMaxDynamicSharedMemorySize, smem_final);

    const int qtiles = (NPIX + QROWS - 1) / QROWS;            // 67

    conv_qkv_kernel<<<dim3(10, 10, 6), 256, smem_qkv>>>(x, wt, wp, wg);
    flash_kernel<<<dim3(qtiles, 2), 256, smem_flash>>>();
    conv_final_kernel<<<dim3(5, HH / 2, 2), 512, smem_final>>>(x, wc, out);
}

// round 14
// speedup vs baseline: 1.0257x; 1.0257x over previous
#include <cuda_runtime.h>
#include <math.h>

#define HH 80
#define WW 80
#define CI 256
#define NF 128
#define NPIX (HH*WW)   // 6400
#define BATCH 2

// Scratch (device globals; no allocations allowed)
__device__ float g_qkv[3][BATCH][NPIX*NF];   // theta, phi(flat), g
__device__ float g_att[BATCH][NPIX*NF];      // attention output (n, c)

// ---------------- packed f32x2 helpers (FFMA2 via PTX) ----------------------
typedef unsigned long long ull;

__device__ __forceinline__ ull pack2(float lo, float hi) {
    ull r; asm("mov.b64 %0, {%1, %2};" : "=l"(r) : "f"(lo), "f"(hi)); return r;
}
__device__ __forceinline__ ull dup2(float v) { return pack2(v, v); }
__device__ __forceinline__ void fma2(ull& d, ull a, ull b) {
    asm("fma.rn.f32x2 %0, %1, %2, %3;" : "=l"(d) : "l"(a), "l"(b), "l"(d));
}
__device__ __forceinline__ ull mul2(ull a, ull b) {
    ull r; asm("mul.rn.f32x2 %0, %1, %2;" : "=l"(r) : "l"(a), "l"(b)); return r;
}
__device__ __forceinline__ float2 unpk(ull v) {
    float2 f; asm("mov.b64 {%0, %1}, %2;" : "=f"(f.x), "=f"(f.y) : "l"(v)); return f;
}

// ---------------------------------------------------------------------------
// Conv 3x3 SAME, CIN=256 -> CO=128 (theta/phi/g).  R11-exact (measured 564us)
// Tile: 4 rows x 16 px x 128 co. Block 256 threads. ci split into two
// 128-channel staging phases -> smem 60KB -> 3 CTAs/SM (24 warps).
// ---------------------------------------------------------------------------
#define PADQ 20
#define QR 4
#define CIH 128
__global__ __launch_bounds__(256) void conv_qkv_kernel(
    const float* __restrict__ x,
    const float* __restrict__ w0,
    const float* __restrict__ w1,
    const float* __restrict__ w2)
{
    extern __shared__ float s_in[];            // [6][CIH][PADQ] (18 used)
    const int x0 = blockIdx.x * 16;
    const int y0 = blockIdx.y * QR;
    const int b  = blockIdx.z / 3;
    const int cv = blockIdx.z % 3;
    const float* __restrict__ wgt = (cv == 0) ? w0 : ((cv == 1) ? w1 : w2);
    float* __restrict__ outp = g_qkv[cv][b];
    const int t = threadIdx.x;

    const int c2 = (t & 63) * 2;
    const int r  = t >> 6;    // 0..3

    ull acc[16];
#pragma unroll
    for (int p = 0; p < 16; p++) acc[p] = dup2(0.f);

    const int kstride = CI * NF;   // weight offset per kx

#pragma unroll 1
    for (int phase = 0; phase < 2; phase++) {
        const int cibase = phase * CIH;
        if (phase) __syncthreads();   // protect smem reuse between phases
        for (int i = t; i < (QR + 2) * 18 * CIH; i += 256) {
            int ci = i & (CIH - 1);
            int xi = (i >> 7) % 18;
            int rr = i / (18 * CIH);
            int gy = y0 - 1 + rr, gx = x0 - 1 + xi;
            float v = 0.f;
            if (gy >= 0 && gy < HH && gx >= 0 && gx < WW)
                v = x[((b * HH + gy) * WW + gx) * CI + cibase + ci];
            s_in[(rr * CIH + ci) * PADQ + xi] = v;
        }
        __syncthreads();

        for (int ky = 0; ky < 3; ky++) {
            const float* srow0 = &s_in[((r + ky) * CIH) * PADQ];
            const float* wbase = &wgt[(ky * 3 * CI + cibase) * NF + c2];
            ull a0 = *(const ull*)&wbase[0];
            ull a1 = *(const ull*)&wbase[kstride];
            ull a2 = *(const ull*)&wbase[2 * kstride];
            ull e0 = *(const ull*)&wbase[NF];
            ull e1 = *(const ull*)&wbase[kstride + NF];
            ull e2 = *(const ull*)&wbase[2 * kstride + NF];
#pragma unroll 1
            for (int ci = 0; ci < CIH; ci += 2) {
                ull u0 = a0, u1 = a1, u2 = a2;
                ull v0 = e0, v1 = e1, v2 = e2;
                if (ci + 2 < CIH) {
                    const float* wn = wbase + (ci + 2) * NF;
                    a0 = *(const ull*)&wn[0];
                    a1 = *(const ull*)&wn[kstride];
                    a2 = *(const ull*)&wn[2 * kstride];
                    e0 = *(const ull*)&wn[NF];
                    e1 = *(const ull*)&wn[kstride + NF];
                    e2 = *(const ull*)&wn[2 * kstride + NF];
                }
#pragma unroll
                for (int half = 0; half < 2; half++) {
                    const float* row = srow0 + (ci + half) * PADQ;
                    float4 wA = *(const float4*)&row[0];
                    float4 wB = *(const float4*)&row[4];
                    float4 wC = *(const float4*)&row[8];
                    float4 wD = *(const float4*)&row[12];
                    float2 wE = *(const float2*)&row[16];
                    ull wd[18];
                    wd[0]=dup2(wA.x);  wd[1]=dup2(wA.y);  wd[2]=dup2(wA.z);  wd[3]=dup2(wA.w);
                    wd[4]=dup2(wB.x);  wd[5]=dup2(wB.y);  wd[6]=dup2(wB.z);  wd[7]=dup2(wB.w);
                    wd[8]=dup2(wC.x);  wd[9]=dup2(wC.y);  wd[10]=dup2(wC.z); wd[11]=dup2(wC.w);
                    wd[12]=dup2(wD.x); wd[13]=dup2(wD.y); wd[14]=dup2(wD.z); wd[15]=dup2(wD.w);
                    wd[16]=dup2(wE.x); wd[17]=dup2(wE.y);
                    ull wv0 = half ? v0 : u0;
                    ull wv1 = half ? v1 : u1;
                    ull wv2 = half ? v2 : u2;
#pragma unroll
                    for (int p = 0; p < 16; p++) {
                        fma2(acc[p], wd[p],     wv0);
                        fma2(acc[p], wd[p + 1], wv1);
                        fma2(acc[p], wd[p + 2], wv2);
                    }
                }
            }
        }
    }
    const int nbase = (y0 + r) * WW + x0;
#pragma unroll
    for (int p = 0; p < 16; p++) {
        float2 v = unpk(acc[p]);
        *(float2*)&outp[(nbase + p) * NF + c2] = v;
    }
}

// ---------------------------------------------------------------------------
// Flash attention: R8 shape (256t, frag 6x8, QROWS=96) + dedicated P buffer
// -> 3 syncthreads per chunk instead of 4.
// smem (floats): Q 128*100 + B 128*128 + G 128*128 + P 96*128 = 57856
//              = 231424 bytes (fits 227KB max dynamic smem).
// All GEMM smem reads are same-row-across-warp -> LD=128 is conflict-free.
// ---------------------------------------------------------------------------
#define LD  128
#define LDQ 100
#define LDP 128
#define QROWS 96
#define SM_Q 0
#define SM_B (128*LDQ)
#define SM_G (128*LDQ + 128*LD)
#define SM_P (128*LDQ + 2*128*LD)
#define SMEM_FLASH ((128*LDQ + 2*128*LD + QROWS*LDP) * 4)

__global__ __launch_bounds__(256, 1) void flash_kernel()
{
    extern __shared__ float sm[];
    float* Qst = sm + SM_Q;   // [c][i] transposed, i < 96
    float* Bs  = sm + SM_B;   // K-chunk
    float* Gs  = sm + SM_G;   // G-chunk
    float* Ps  = sm + SM_P;   // P (separate buffer, 96 x 128)

    const int b  = blockIdx.y;
    const int q0 = blockIdx.x * QROWS;
    const float* __restrict__ theta = g_qkv[0][b];
    const float* __restrict__ phi   = g_qkv[1][b];
    const float* __restrict__ gmat  = g_qkv[2][b];

    const int t  = threadIdx.x;
    const int tx = t & 15, ty = t >> 4;
    const int i0 = ty * 6, j0 = tx * 8;

    for (int idx = t; idx < QROWS * 128; idx += 256) {
        int i = idx >> 7, c = idx & 127;
        int qi = q0 + i; if (qi >= NPIX) qi = NPIX - 1;
        Qst[c * LDQ + i] = theta[qi * NF + c];
    }

    ull o2[6][4];
    float mrun[6], lrun[6];
#pragma unroll
    for (int ii = 0; ii < 6; ii++) {
        mrun[ii] = -1e30f; lrun[ii] = 0.f;
#pragma unroll
        for (int cp = 0; cp < 4; cp++) o2[ii][cp] = dup2(0.f);
    }
    __syncthreads();

    for (int km = 0; km < 50; km++) {
        const int m0 = km * 128;
        for (int idx = t; idx < 4096; idx += 256) {
            int rr = idx >> 5;
            int cc = (idx & 31) << 2;
            *(float4*)&Bs[rr * LD + cc] = *(const float4*)&phi[rr * NPIX + m0 + cc];
            *(float4*)&Gs[rr * LD + cc] = *(const float4*)&gmat[(m0 + rr) * NF + cc];
        }
        __syncthreads();                 // (1) staging visible

        ull s2[6][4];
#pragma unroll
        for (int ii = 0; ii < 6; ii++)
#pragma unroll
            for (int jp = 0; jp < 4; jp++) s2[ii][jp] = dup2(0.f);

#pragma unroll 1
        for (int c = 0; c < 128; c += 2) {
#pragma unroll
            for (int cc2 = 0; cc2 < 2; cc2++) {
                const float* qrow = &Qst[(c + cc2) * LDQ + i0];
                float2 a01 = *(const float2*)&qrow[0];
                float2 a23 = *(const float2*)&qrow[2];
                float2 a45 = *(const float2*)&qrow[4];
                ull av[6] = {dup2(a01.x), dup2(a01.y), dup2(a23.x),
                             dup2(a23.y), dup2(a45.x), dup2(a45.y)};
                const ulonglong2* brow = (const ulonglong2*)&Bs[(c + cc2) * LD + j0];
                ulonglong2 b01 = brow[0], b23 = brow[1];
                ull bv[4] = {b01.x, b01.y, b23.x, b23.y};
#pragma unroll
                for (int ii = 0; ii < 6; ii++)
#pragma unroll
                    for (int jp = 0; jp < 4; jp++)
                        fma2(s2[ii][jp], av[ii], bv[jp]);
            }
        }
        // NO sync here: P goes to its own buffer, Bs stays intact

#pragma unroll
        for (int ii = 0; ii < 6; ii++) {
            float sv[8];
            float2 u;
            u = unpk(s2[ii][0]); sv[0] = u.x; sv[1] = u.y;
            u = unpk(s2[ii][1]); sv[2] = u.x; sv[3] = u.y;
            u = unpk(s2[ii][2]); sv[4] = u.x; sv[5] = u.y;
            u = unpk(s2[ii][3]); sv[6] = u.x; sv[7] = u.y;
            float mx = sv[0];
#pragma unroll
            for (int jj = 1; jj < 8; jj++) mx = fmaxf(mx, sv[jj]);
            mx = fmaxf(mx, __shfl_xor_sync(0xffffffffu, mx, 1));
            mx = fmaxf(mx, __shfl_xor_sync(0xffffffffu, mx, 2));
            mx = fmaxf(mx, __shfl_xor_sync(0xffffffffu, mx, 4));
            mx = fmaxf(mx, __shfl_xor_sync(0xffffffffu, mx, 8));
            float mnew = fmaxf(mrun[ii], mx);
            float f = __expf(mrun[ii] - mnew);
            mrun[ii] = mnew;
            float sum = 0.f;
#pragma unroll
            for (int jj = 0; jj < 8; jj++) {
                float p = __expf(sv[jj] - mnew);
                sv[jj] = p;
                sum += p;
            }
            sum += __shfl_xor_sync(0xffffffffu, sum, 1);
            sum += __shfl_xor_sync(0xffffffffu, sum, 2);
            sum += __shfl_xor_sync(0xffffffffu, sum, 4);
            sum += __shfl_xor_sync(0xffffffffu, sum, 8);
            lrun[ii] = lrun[ii] * f + sum;
            ull f2v = dup2(f);
#pragma unroll
            for (int cp = 0; cp < 4; cp++)
                o2[ii][cp] = mul2(o2[ii][cp], f2v);
            *(float4*)&Ps[(i0 + ii) * LDP + j0]     = make_float4(sv[0], sv[1], sv[2], sv[3]);
            *(float4*)&Ps[(i0 + ii) * LDP + j0 + 4] = make_float4(sv[4], sv[5], sv[6], sv[7]);
        }
        __syncthreads();                 // (2) all P visible

#pragma unroll 1
        for (int j4 = 0; j4 < 128; j4 += 4) {
            float4 pv4[6];
#pragma unroll
            for (int ii = 0; ii < 6; ii++)
                pv4[ii] = *(const float4*)&Ps[(i0 + ii) * LDP + j4];
#pragma unroll
            for (int jj = 0; jj < 4; jj++) {
                const ulonglong2* grow = (const ulonglong2*)&Gs[(j4 + jj) * LD + j0];
                ulonglong2 g01 = grow[0], g23 = grow[1];
                ull gv[4] = {g01.x, g01.y, g23.x, g23.y};
#pragma unroll
                for (int ii = 0; ii < 6; ii++) {
                    float pj = (jj == 0) ? pv4[ii].x : (jj == 1) ? pv4[ii].y
                             : (jj == 2) ? pv4[ii].z : pv4[ii].w;
                    ull pv = dup2(pj);
#pragma unroll
                    for (int cp = 0; cp < 4; cp++)
                        fma2(o2[ii][cp], pv, gv[cp]);
                }
            }
        }
        __syncthreads();                 // (3) GEMM2 done before next staging
    }

#pragma unroll
    for (int ii = 0; ii < 6; ii++) {
        int row = q0 + i0 + ii;
        if (row >= NPIX) continue;
        float inv = 1.f / lrun[ii];
        float2 v0 = unpk(o2[ii][0]), v1 = unpk(o2[ii][1]);
        float2 v2 = unpk(o2[ii][2]), v3 = unpk(o2[ii][3]);
        float* dst = &g_att[b][row * NF + j0];
        *(float4*)&dst[0] = make_float4(v0.x * inv, v0.y * inv, v1.x * inv, v1.y * inv);
        *(float4*)&dst[4] = make_float4(v2.x * inv, v2.y * inv, v3.x * inv, v3.y * inv);
    }
}

// ---------------------------------------------------------------------------
// Final conv 3x3, 128 -> 256, + residual add, writes d_out. (R8 exact)
// Tile: 2 rows x 16 px x 256 co. Block 512 threads.
// ---------------------------------------------------------------------------
#define PADF 20
__global__ __launch_bounds__(512) void conv_final_kernel(
    const float* __restrict__ x,
    const float* __restrict__ wc,
    float* __restrict__ out)
{
    extern __shared__ float s_in[];            // [4][NF][PADF]
    const int x0 = blockIdx.x * 16;
    const int y0 = blockIdx.y * 2;
    const int b  = blockIdx.z;
    const int t  = threadIdx.x;
    const float* __restrict__ ain = g_att[b];

    for (int i = t; i < 4 * 18 * NF; i += 512) {
        int ci = i & (NF - 1);
        int xi = (i >> 7) % 18;
        int r  = i / (18 * NF);
        int gy = y0 - 1 + r, gx = x0 - 1 + xi;
        float v = 0.f;
        if (gy >= 0 && gy < HH && gx >= 0 && gx < WW)
            v = ain[(gy * WW + gx) * NF + ci];
        s_in[(r * NF + ci) * PADF + xi] = v;
    }
    __syncthreads();

    const int c2  = (t & 127) * 2;
    const int pxb = ((t >> 7) & 1) * 8;
    const int r   = t >> 8;

    ull acc[8];
#pragma unroll
    for (int p = 0; p < 8; p++) acc[p] = dup2(0.f);

    const int kstride = NF * CI;

    for (int ky = 0; ky < 3; ky++) {
        const float* srow0 = &s_in[((r + ky) * NF) * PADF + pxb];
        const float* wbase = &wc[(ky * 3 * NF) * CI + c2];
        ull a0 = *(const ull*)&wbase[0];
        ull a1 = *(const ull*)&wbase[kstride];
        ull a2 = *(const ull*)&wbase[2 * kstride];
        ull e0 = *(const ull*)&wbase[CI];
        ull e1 = *(const ull*)&wbase[kstride + CI];
        ull e2 = *(const ull*)&wbase[2 * kstride + CI];
#pragma unroll 1
        for (int ci = 0; ci < NF; ci += 2) {
            ull u0 = a0, u1 = a1, u2 = a2;
            ull v0 = e0, v1 = e1, v2 = e2;
            if (ci + 2 < NF) {
                const float* wn = wbase + (ci + 2) * CI;
                a0 = *(const ull*)&wn[0];
                a1 = *(const ull*)&wn[kstride];
                a2 = *(const ull*)&wn[2 * kstride];
                e0 = *(const ull*)&wn[CI];
                e1 = *(const ull*)&wn[kstride + CI];
                e2 = *(const ull*)&wn[2 * kstride + CI];
            }
#pragma unroll
            for (int half = 0; half < 2; half++) {
                const float* row = srow0 + (ci + half) * PADF;
                float4 wA = *(const float4*)&row[0];
                float4 wB = *(const float4*)&row[4];
                float2 wE = *(const float2*)&row[8];
                ull wd[10];
                wd[0]=dup2(wA.x); wd[1]=dup2(wA.y); wd[2]=dup2(wA.z); wd[3]=dup2(wA.w);
                wd[4]=dup2(wB.x); wd[5]=dup2(wB.y); wd[6]=dup2(wB.z); wd[7]=dup2(wB.w);
                wd[8]=dup2(wE.x); wd[9]=dup2(wE.y);
                ull wv0 = half ? v0 : u0;
                ull wv1 = half ? v1 : u1;
                ull wv2 = half ? v2 : u2;
#pragma unroll
                for (int p = 0; p < 8; p++) {
                    fma2(acc[p], wd[p],     wv0);
                    fma2(acc[p], wd[p + 1], wv1);
                    fma2(acc[p], wd[p + 2], wv2);
                }
            }
        }
    }
#pragma unroll
    for (int p = 0; p < 8; p++) {
        float2 v = unpk(acc[p]);
        int gi = ((b * HH + y0 + r) * WW + x0 + pxb + p) * CI + c2;
        float2 xv = *(const float2*)&x[gi];
        *(float2*)&out[gi] = make_float2(xv.x + v.x, xv.y + v.y);
    }
}

// ---------------------------------------------------------------------------
extern "C" void kernel_launch(void* const* d_in, const int* in_sizes, int n_in,
                              void* d_out, int out_size)
{
    const float* x  = (const float*)d_in[0];
    const float* wt = (const float*)d_in[1];
    const float* wp = (const float*)d_in[2];
    const float* wg = (const float*)d_in[3];
    const float* wc = (const float*)d_in[4];
    float* out = (float*)d_out;

    const int smem_qkv   = (QR + 2) * CIH * PADQ * 4;         // 61440
    const int smem_flash = SMEM_FLASH;                        // 231424
    const int smem_final = 4 * NF * PADF * 4;                 // 40960

    cudaFuncSetAttribute(conv_qkv_kernel,   cudaFuncAttributeMaxDynamicSharedMemorySize, smem_qkv);
    cudaFuncSetAttribute(flash_kernel,      cudaFuncAttributeMaxDynamicSharedMemorySize, smem_flash);
    cudaFuncSetAttribute(conv_final_kernel, cudaFuncAttributeMaxDynamicSharedMemorySize, smem_final);

    const int qtiles = (NPIX + QROWS - 1) / QROWS;            // 67

    conv_qkv_kernel<<<dim3(5, HH / QR, 6), 256, smem_qkv>>>(x, wt, wp, wg);
    flash_kernel<<<dim3(qtiles, 2), 256, smem_flash>>>();
    conv_final_kernel<<<dim3(5, HH / 2, 2), 512, smem_final>>>(x, wc, out);
}

// round 15
// speedup vs baseline: 1.0448x; 1.0187x over previous
#include <cuda_runtime.h>
#include <math.h>

#define HH 80
#define WW 80
#define CI 256
#define NF 128
#define NPIX (HH*WW)   // 6400
#define BATCH 2

// Scratch (device globals; no allocations allowed)
__device__ float g_qkv[3][BATCH][NPIX*NF];   // theta, phi(flat), g
__device__ float g_att[BATCH][NPIX*NF];      // attention output (n, c)

// ---------------- packed f32x2 helpers (FFMA2 via PTX) ----------------------
typedef unsigned long long ull;

__device__ __forceinline__ ull pack2(float lo, float hi) {
    ull r; asm("mov.b64 %0, {%1, %2};" : "=l"(r) : "f"(lo), "f"(hi)); return r;
}
__device__ __forceinline__ ull dup2(float v) { return pack2(v, v); }
__device__ __forceinline__ void fma2(ull& d, ull a, ull b) {
    asm("fma.rn.f32x2 %0, %1, %2, %3;" : "=l"(d) : "l"(a), "l"(b), "l"(d));
}
__device__ __forceinline__ ull mul2(ull a, ull b) {
    ull r; asm("mul.rn.f32x2 %0, %1, %2;" : "=l"(r) : "l"(a), "l"(b)); return r;
}
__device__ __forceinline__ float2 unpk(ull v) {
    float2 f; asm("mov.b64 {%0, %1}, %2;" : "=f"(f.x), "=f"(f.y) : "l"(v)); return f;
}

// ---------------------------------------------------------------------------
// Conv 3x3 SAME, CIN=256 -> CO=128 (theta/phi/g).
// Tile: 2 rows x 16 px x 128 co. Block 128 threads (4 warps), smem 40KB
// -> 5 CTAs/SM (20 warps). Same 16px x 2co inner loop as R11 (measured-best).
// Grid 1200 -> 1.62 waves of short tasks (vs 1.35 waves of long tasks).
// ---------------------------------------------------------------------------
#define PADQ 20
#define QR 2
#define CIH 128
__global__ __launch_bounds__(128) void conv_qkv_kernel(
    const float* __restrict__ x,
    const float* __restrict__ w0,
    const float* __restrict__ w1,
    const float* __restrict__ w2)
{
    extern __shared__ float s_in[];            // [4][CIH][PADQ] (18 used)
    const int x0 = blockIdx.x * 16;
    const int y0 = blockIdx.y * QR;
    const int b  = blockIdx.z / 3;
    const int cv = blockIdx.z % 3;
    const float* __restrict__ wgt = (cv == 0) ? w0 : ((cv == 1) ? w1 : w2);
    float* __restrict__ outp = g_qkv[cv][b];
    const int t = threadIdx.x;

    const int c2 = (t & 63) * 2;
    const int r  = t >> 6;    // 0..1

    ull acc[16];
#pragma unroll
    for (int p = 0; p < 16; p++) acc[p] = dup2(0.f);

    const int kstride = CI * NF;   // weight offset per kx

#pragma unroll 1
    for (int phase = 0; phase < 2; phase++) {
        const int cibase = phase * CIH;
        if (phase) __syncthreads();   // protect smem reuse between phases
        for (int i = t; i < (QR + 2) * 18 * CIH; i += 128) {
            int ci = i & (CIH - 1);
            int xi = (i >> 7) % 18;
            int rr = i / (18 * CIH);
            int gy = y0 - 1 + rr, gx = x0 - 1 + xi;
            float v = 0.f;
            if (gy >= 0 && gy < HH && gx >= 0 && gx < WW)
                v = x[((b * HH + gy) * WW + gx) * CI + cibase + ci];
            s_in[(rr * CIH + ci) * PADQ + xi] = v;
        }
        __syncthreads();

        for (int ky = 0; ky < 3; ky++) {
            const float* srow0 = &s_in[((r + ky) * CIH) * PADQ];
            const float* wbase = &wgt[(ky * 3 * CI + cibase) * NF + c2];
            ull a0 = *(const ull*)&wbase[0];
            ull a1 = *(const ull*)&wbase[kstride];
            ull a2 = *(const ull*)&wbase[2 * kstride];
            ull e0 = *(const ull*)&wbase[NF];
            ull e1 = *(const ull*)&wbase[kstride + NF];
            ull e2 = *(const ull*)&wbase[2 * kstride + NF];
#pragma unroll 1
            for (int ci = 0; ci < CIH; ci += 2) {
                ull u0 = a0, u1 = a1, u2 = a2;
                ull v0 = e0, v1 = e1, v2 = e2;
                if (ci + 2 < CIH) {
                    const float* wn = wbase + (ci + 2) * NF;
                    a0 = *(const ull*)&wn[0];
                    a1 = *(const ull*)&wn[kstride];
                    a2 = *(const ull*)&wn[2 * kstride];
                    e0 = *(const ull*)&wn[NF];
                    e1 = *(const ull*)&wn[kstride + NF];
                    e2 = *(const ull*)&wn[2 * kstride + NF];
                }
#pragma unroll
                for (int half = 0; half < 2; half++) {
                    const float* row = srow0 + (ci + half) * PADQ;
                    float4 wA = *(const float4*)&row[0];
                    float4 wB = *(const float4*)&row[4];
                    float4 wC = *(const float4*)&row[8];
                    float4 wD = *(const float4*)&row[12];
                    float2 wE = *(const float2*)&row[16];
                    ull wd[18];
                    wd[0]=dup2(wA.x);  wd[1]=dup2(wA.y);  wd[2]=dup2(wA.z);  wd[3]=dup2(wA.w);
                    wd[4]=dup2(wB.x);  wd[5]=dup2(wB.y);  wd[6]=dup2(wB.z);  wd[7]=dup2(wB.w);
                    wd[8]=dup2(wC.x);  wd[9]=dup2(wC.y);  wd[10]=dup2(wC.z); wd[11]=dup2(wC.w);
                    wd[12]=dup2(wD.x); wd[13]=dup2(wD.y); wd[14]=dup2(wD.z); wd[15]=dup2(wD.w);
                    wd[16]=dup2(wE.x); wd[17]=dup2(wE.y);
                    ull wv0 = half ? v0 : u0;
                    ull wv1 = half ? v1 : u1;
                    ull wv2 = half ? v2 : u2;
#pragma unroll
                    for (int p = 0; p < 16; p++) {
                        fma2(acc[p], wd[p],     wv0);
                        fma2(acc[p], wd[p + 1], wv1);
                        fma2(acc[p], wd[p + 2], wv2);
                    }
                }
            }
        }
    }
    const int nbase = (y0 + r) * WW + x0;
#pragma unroll
    for (int p = 0; p < 16; p++) {
        float2 v = unpk(acc[p]);
        *(float2*)&outp[(nbase + p) * NF + c2] = v;
    }
}

// ---------------------------------------------------------------------------
// Flash attention (R11-exact, measured-best ~970us): 256 threads, frag 6x8,
// QROWS=96 -> 134 CTAs, P reuses Bs, float4 P-reads, c-unroll x2.
// ---------------------------------------------------------------------------
#define LD  132
#define LDQ 100
#define QROWS 96
#define SM_Q 0
#define SM_B (128*LDQ)
#define SM_G (128*LDQ + 128*LD)

__global__ __launch_bounds__(256, 1) void flash_kernel()
{
    extern __shared__ float sm[];
    float* Qst = sm + SM_Q;   // [c][i] transposed, i < 96
    float* Bs  = sm + SM_B;   // K-chunk, then reused as P
    float* Gs  = sm + SM_G;

    const int b  = blockIdx.y;
    const int q0 = blockIdx.x * QROWS;
    const float* __restrict__ theta = g_qkv[0][b];
    const float* __restrict__ phi   = g_qkv[1][b];
    const float* __restrict__ gmat  = g_qkv[2][b];

    const int t  = threadIdx.x;
    const int tx = t & 15, ty = t >> 4;
    const int i0 = ty * 6, j0 = tx * 8;

    for (int idx = t; idx < QROWS * 128; idx += 256) {
        int i = idx >> 7, c = idx & 127;
        int qi = q0 + i; if (qi >= NPIX) qi = NPIX - 1;
        Qst[c * LDQ + i] = theta[qi * NF + c];
    }

    ull o2[6][4];
    float mrun[6], lrun[6];
#pragma unroll
    for (int ii = 0; ii < 6; ii++) {
        mrun[ii] = -1e30f; lrun[ii] = 0.f;
#pragma unroll
        for (int cp = 0; cp < 4; cp++) o2[ii][cp] = dup2(0.f);
    }
    __syncthreads();

    for (int km = 0; km < 50; km++) {
        const int m0 = km * 128;
        for (int idx = t; idx < 4096; idx += 256) {
            int rr = idx >> 5;
            int cc = (idx & 31) << 2;
            *(float4*)&Bs[rr * LD + cc] = *(const float4*)&phi[rr * NPIX + m0 + cc];
            *(float4*)&Gs[rr * LD + cc] = *(const float4*)&gmat[(m0 + rr) * NF + cc];
        }
        __syncthreads();

        ull s2[6][4];
#pragma unroll
        for (int ii = 0; ii < 6; ii++)
#pragma unroll
            for (int jp = 0; jp < 4; jp++) s2[ii][jp] = dup2(0.f);

#pragma unroll 1
        for (int c = 0; c < 128; c += 2) {
#pragma unroll
            for (int cc2 = 0; cc2 < 2; cc2++) {
                const float* qrow = &Qst[(c + cc2) * LDQ + i0];
                float2 a01 = *(const float2*)&qrow[0];
                float2 a23 = *(const float2*)&qrow[2];
                float2 a45 = *(const float2*)&qrow[4];
                ull av[6] = {dup2(a01.x), dup2(a01.y), dup2(a23.x),
                             dup2(a23.y), dup2(a45.x), dup2(a45.y)};
                const ulonglong2* brow = (const ulonglong2*)&Bs[(c + cc2) * LD + j0];
                ulonglong2 b01 = brow[0], b23 = brow[1];
                ull bv[4] = {b01.x, b01.y, b23.x, b23.y};
#pragma unroll
                for (int ii = 0; ii < 6; ii++)
#pragma unroll
                    for (int jp = 0; jp < 4; jp++)
                        fma2(s2[ii][jp], av[ii], bv[jp]);
            }
        }
        __syncthreads();

#pragma unroll
        for (int ii = 0; ii < 6; ii++) {
            float sv[8];
            float2 u;
            u = unpk(s2[ii][0]); sv[0] = u.x; sv[1] = u.y;
            u = unpk(s2[ii][1]); sv[2] = u.x; sv[3] = u.y;
            u = unpk(s2[ii][2]); sv[4] = u.x; sv[5] = u.y;
            u = unpk(s2[ii][3]); sv[6] = u.x; sv[7] = u.y;
            float mx = sv[0];
#pragma unroll
            for (int jj = 1; jj < 8; jj++) mx = fmaxf(mx, sv[jj]);
            mx = fmaxf(mx, __shfl_xor_sync(0xffffffffu, mx, 1));
            mx = fmaxf(mx, __shfl_xor_sync(0xffffffffu, mx, 2));
            mx = fmaxf(mx, __shfl_xor_sync(0xffffffffu, mx, 4));
            mx = fmaxf(mx, __shfl_xor_sync(0xffffffffu, mx, 8));
            float mnew = fmaxf(mrun[ii], mx);
            float f = __expf(mrun[ii] - mnew);
            mrun[ii] = mnew;
            float sum = 0.f;
#pragma unroll
            for (int jj = 0; jj < 8; jj++) {
                float p = __expf(sv[jj] - mnew);
                sv[jj] = p;
                sum += p;
            }
            sum += __shfl_xor_sync(0xffffffffu, sum, 1);
            sum += __shfl_xor_sync(0xffffffffu, sum, 2);
            sum += __shfl_xor_sync(0xffffffffu, sum, 4);
            sum += __shfl_xor_sync(0xffffffffu, sum, 8);
            lrun[ii] = lrun[ii] * f + sum;
            ull f2v = dup2(f);
#pragma unroll
            for (int cp = 0; cp < 4; cp++)
                o2[ii][cp] = mul2(o2[ii][cp], f2v);
            *(float4*)&Bs[(i0 + ii) * LD + j0]     = make_float4(sv[0], sv[1], sv[2], sv[3]);
            *(float4*)&Bs[(i0 + ii) * LD + j0 + 4] = make_float4(sv[4], sv[5], sv[6], sv[7]);
        }
        __syncthreads();

#pragma unroll 1
        for (int j4 = 0; j4 < 128; j4 += 4) {
            float4 pv4[6];
#pragma unroll
            for (int ii = 0; ii < 6; ii++)
                pv4[ii] = *(const float4*)&Bs[(i0 + ii) * LD + j4];
#pragma unroll
            for (int jj = 0; jj < 4; jj++) {
                const ulonglong2* grow = (const ulonglong2*)&Gs[(j4 + jj) * LD + j0];
                ulonglong2 g01 = grow[0], g23 = grow[1];
                ull gv[4] = {g01.x, g01.y, g23.x, g23.y};
#pragma unroll
                for (int ii = 0; ii < 6; ii++) {
                    float pj = (jj == 0) ? pv4[ii].x : (jj == 1) ? pv4[ii].y
                             : (jj == 2) ? pv4[ii].z : pv4[ii].w;
                    ull pv = dup2(pj);
#pragma unroll
                    for (int cp = 0; cp < 4; cp++)
                        fma2(o2[ii][cp], pv, gv[cp]);
                }
            }
        }
        __syncthreads();
    }

#pragma unroll
    for (int ii = 0; ii < 6; ii++) {
        int row = q0 + i0 + ii;
        if (row >= NPIX) continue;
        float inv = 1.f / lrun[ii];
        float2 v0 = unpk(o2[ii][0]), v1 = unpk(o2[ii][1]);
        float2 v2 = unpk(o2[ii][2]), v3 = unpk(o2[ii][3]);
        float* dst = &g_att[b][row * NF + j0];
        *(float4*)&dst[0] = make_float4(v0.x * inv, v0.y * inv, v1.x * inv, v1.y * inv);
        *(float4*)&dst[4] = make_float4(v2.x * inv, v2.y * inv, v3.x * inv, v3.y * inv);
    }
}

// ---------------------------------------------------------------------------
// Final conv 3x3, 128 -> 256, + residual add, writes d_out. (R8 exact)
// Tile: 2 rows x 16 px x 256 co. Block 512 threads.
// ---------------------------------------------------------------------------
#define PADF 20
__global__ __launch_bounds__(512) void conv_final_kernel(
    const float* __restrict__ x,
    const float* __restrict__ wc,
    float* __restrict__ out)
{
    extern __shared__ float s_in[];            // [4][NF][PADF]
    const int x0 = blockIdx.x * 16;
    const int y0 = blockIdx.y * 2;
    const int b  = blockIdx.z;
    const int t  = threadIdx.x;
    const float* __restrict__ ain = g_att[b];

    for (int i = t; i < 4 * 18 * NF; i += 512) {
        int ci = i & (NF - 1);
        int xi = (i >> 7) % 18;
        int r  = i / (18 * NF);
        int gy = y0 - 1 + r, gx = x0 - 1 + xi;
        float v = 0.f;
        if (gy >= 0 && gy < HH && gx >= 0 && gx < WW)
            v = ain[(gy * WW + gx) * NF + ci];
        s_in[(r * NF + ci) * PADF + xi] = v;
    }
    __syncthreads();

    const int c2  = (t & 127) * 2;
    const int pxb = ((t >> 7) & 1) * 8;
    const int r   = t >> 8;

    ull acc[8];
#pragma unroll
    for (int p = 0; p < 8; p++) acc[p] = dup2(0.f);

    const int kstride = NF * CI;

    for (int ky = 0; ky < 3; ky++) {
        const float* srow0 = &s_in[((r + ky) * NF) * PADF + pxb];
        const float* wbase = &wc[(ky * 3 * NF) * CI + c2];
        ull a0 = *(const ull*)&wbase[0];
        ull a1 = *(const ull*)&wbase[kstride];
        ull a2 = *(const ull*)&wbase[2 * kstride];
        ull e0 = *(const ull*)&wbase[CI];
        ull e1 = *(const ull*)&wbase[kstride + CI];
        ull e2 = *(const ull*)&wbase[2 * kstride + CI];
#pragma unroll 1
        for (int ci = 0; ci < NF; ci += 2) {
            ull u0 = a0, u1 = a1, u2 = a2;
            ull v0 = e0, v1 = e1, v2 = e2;
            if (ci + 2 < NF) {
                const float* wn = wbase + (ci + 2) * CI;
                a0 = *(const ull*)&wn[0];
                a1 = *(const ull*)&wn[kstride];
                a2 = *(const ull*)&wn[2 * kstride];
                e0 = *(const ull*)&wn[CI];
                e1 = *(const ull*)&wn[kstride + CI];
                e2 = *(const ull*)&wn[2 * kstride + CI];
            }
#pragma unroll
            for (int half = 0; half < 2; half++) {
                const float* row = srow0 + (ci + half) * PADF;
                float4 wA = *(const float4*)&row[0];
                float4 wB = *(const float4*)&row[4];
                float2 wE = *(const float2*)&row[8];
                ull wd[10];
                wd[0]=dup2(wA.x); wd[1]=dup2(wA.y); wd[2]=dup2(wA.z); wd[3]=dup2(wA.w);
                wd[4]=dup2(wB.x); wd[5]=dup2(wB.y); wd[6]=dup2(wB.z); wd[7]=dup2(wB.w);
                wd[8]=dup2(wE.x); wd[9]=dup2(wE.y);
                ull wv0 = half ? v0 : u0;
                ull wv1 = half ? v1 : u1;
                ull wv2 = half ? v2 : u2;
#pragma unroll
                for (int p = 0; p < 8; p++) {
                    fma2(acc[p], wd[p],     wv0);
                    fma2(acc[p], wd[p + 1], wv1);
                    fma2(acc[p], wd[p + 2], wv2);
                }
            }
        }
    }
#pragma unroll
    for (int p = 0; p < 8; p++) {
        float2 v = unpk(acc[p]);
        int gi = ((b * HH + y0 + r) * WW + x0 + pxb + p) * CI + c2;
        float2 xv = *(const float2*)&x[gi];
        *(float2*)&out[gi] = make_float2(xv.x + v.x, xv.y + v.y);
    }
}

// ---------------------------------------------------------------------------
extern "C" void kernel_launch(void* const* d_in, const int* in_sizes, int n_in,
                              void* d_out, int out_size)
{
    const float* x  = (const float*)d_in[0];
    const float* wt = (const float*)d_in[1];
    const float* wp = (const float*)d_in[2];
    const float* wg = (const float*)d_in[3];
    const float* wc = (const float*)d_in[4];
    float* out = (float*)d_out;

    const int smem_qkv   = (QR + 2) * CIH * PADQ * 4;         // 40960
    const int smem_flash = (128 * LDQ + 2 * 128 * LD) * 4;    // 186368
    const int smem_final = 4 * NF * PADF * 4;                 // 40960

    cudaFuncSetAttribute(conv_qkv_kernel,   cudaFuncAttributeMaxDynamicSharedMemorySize, smem_qkv);
    cudaFuncSetAttribute(flash_kernel,      cudaFuncAttributeMaxDynamicSharedMemorySize, smem_flash);
    cudaFuncSetAttribute(conv_final_kernel, cudaFuncAttributeMaxDynamicSharedMemorySize, smem_final);

    const int qtiles = (NPIX + QROWS - 1) / QROWS;            // 67

    conv_qkv_kernel<<<dim3(5, HH / QR, 6), 128, smem_qkv>>>(x, wt, wp, wg);
    flash_kernel<<<dim3(qtiles, 2), 256, smem_flash>>>();
    conv_final_kernel<<<dim3(5, HH / 2, 2), 512, smem_final>>>(x, wc, out);
}

// round 16
// speedup vs baseline: 1.0555x; 1.0102x over previous
#include <cuda_runtime.h>
#include <math.h>

#define HH 80
#define WW 80
#define CI 256
#define NF 128
#define NPIX (HH*WW)   // 6400
#define BATCH 2

// Scratch (device globals; no allocations allowed)
__device__ float g_qkv[3][BATCH][NPIX*NF];   // theta, phi(flat), g
__device__ float g_att[BATCH][NPIX*NF];      // attention output (n, c)

// ---------------- packed f32x2 helpers (FFMA2 via PTX) ----------------------
typedef unsigned long long ull;

__device__ __forceinline__ ull pack2(float lo, float hi) {
    ull r; asm("mov.b64 %0, {%1, %2};" : "=l"(r) : "f"(lo), "f"(hi)); return r;
}
__device__ __forceinline__ ull dup2(float v) { return pack2(v, v); }
__device__ __forceinline__ void fma2(ull& d, ull a, ull b) {
    asm("fma.rn.f32x2 %0, %1, %2, %3;" : "=l"(d) : "l"(a), "l"(b), "l"(d));
}
__device__ __forceinline__ ull mul2(ull a, ull b) {
    ull r; asm("mul.rn.f32x2 %0, %1, %2;" : "=l"(r) : "l"(a), "l"(b)); return r;
}
__device__ __forceinline__ float2 unpk(ull v) {
    float2 f; asm("mov.b64 {%0, %1}, %2;" : "=f"(f.x), "=f"(f.y) : "l"(v)); return f;
}

// ---------------------------------------------------------------------------
// Conv 3x3 SAME, CIN=256 -> CO=128 (theta/phi/g).  R15-exact (measured 494us)
// Tile: 2 rows x 16 px x 128 co. Block 128 threads, smem 40KB -> 5 CTAs/SM.
// ---------------------------------------------------------------------------
#define PADQ 20
#define QR 2
#define CIH 128
__global__ __launch_bounds__(128) void conv_qkv_kernel(
    const float* __restrict__ x,
    const float* __restrict__ w0,
    const float* __restrict__ w1,
    const float* __restrict__ w2)
{
    extern __shared__ float s_in[];            // [4][CIH][PADQ] (18 used)
    const int x0 = blockIdx.x * 16;
    const int y0 = blockIdx.y * QR;
    const int b  = blockIdx.z / 3;
    const int cv = blockIdx.z % 3;
    const float* __restrict__ wgt = (cv == 0) ? w0 : ((cv == 1) ? w1 : w2);
    float* __restrict__ outp = g_qkv[cv][b];
    const int t = threadIdx.x;

    const int c2 = (t & 63) * 2;
    const int r  = t >> 6;    // 0..1

    ull acc[16];
#pragma unroll
    for (int p = 0; p < 16; p++) acc[p] = dup2(0.f);

    const int kstride = CI * NF;   // weight offset per kx

#pragma unroll 1
    for (int phase = 0; phase < 2; phase++) {
        const int cibase = phase * CIH;
        if (phase) __syncthreads();   // protect smem reuse between phases
        for (int i = t; i < (QR + 2) * 18 * CIH; i += 128) {
            int ci = i & (CIH - 1);
            int xi = (i >> 7) % 18;
            int rr = i / (18 * CIH);
            int gy = y0 - 1 + rr, gx = x0 - 1 + xi;
            float v = 0.f;
            if (gy >= 0 && gy < HH && gx >= 0 && gx < WW)
                v = x[((b * HH + gy) * WW + gx) * CI + cibase + ci];
            s_in[(rr * CIH + ci) * PADQ + xi] = v;
        }
        __syncthreads();

        for (int ky = 0; ky < 3; ky++) {
            const float* srow0 = &s_in[((r + ky) * CIH) * PADQ];
            const float* wbase = &wgt[(ky * 3 * CI + cibase) * NF + c2];
            ull a0 = *(const ull*)&wbase[0];
            ull a1 = *(const ull*)&wbase[kstride];
            ull a2 = *(const ull*)&wbase[2 * kstride];
            ull e0 = *(const ull*)&wbase[NF];
            ull e1 = *(const ull*)&wbase[kstride + NF];
            ull e2 = *(const ull*)&wbase[2 * kstride + NF];
#pragma unroll 1
            for (int ci = 0; ci < CIH; ci += 2) {
                ull u0 = a0, u1 = a1, u2 = a2;
                ull v0 = e0, v1 = e1, v2 = e2;
                if (ci + 2 < CIH) {
                    const float* wn = wbase + (ci + 2) * NF;
                    a0 = *(const ull*)&wn[0];
                    a1 = *(const ull*)&wn[kstride];
                    a2 = *(const ull*)&wn[2 * kstride];
                    e0 = *(const ull*)&wn[NF];
                    e1 = *(const ull*)&wn[kstride + NF];
                    e2 = *(const ull*)&wn[2 * kstride + NF];
                }
#pragma unroll
                for (int half = 0; half < 2; half++) {
                    const float* row = srow0 + (ci + half) * PADQ;
                    float4 wA = *(const float4*)&row[0];
                    float4 wB = *(const float4*)&row[4];
                    float4 wC = *(const float4*)&row[8];
                    float4 wD = *(const float4*)&row[12];
                    float2 wE = *(const float2*)&row[16];
                    ull wd[18];
                    wd[0]=dup2(wA.x);  wd[1]=dup2(wA.y);  wd[2]=dup2(wA.z);  wd[3]=dup2(wA.w);
                    wd[4]=dup2(wB.x);  wd[5]=dup2(wB.y);  wd[6]=dup2(wB.z);  wd[7]=dup2(wB.w);
                    wd[8]=dup2(wC.x);  wd[9]=dup2(wC.y);  wd[10]=dup2(wC.z); wd[11]=dup2(wC.w);
                    wd[12]=dup2(wD.x); wd[13]=dup2(wD.y); wd[14]=dup2(wD.z); wd[15]=dup2(wD.w);
                    wd[16]=dup2(wE.x); wd[17]=dup2(wE.y);
                    ull wv0 = half ? v0 : u0;
                    ull wv1 = half ? v1 : u1;
                    ull wv2 = half ? v2 : u2;
#pragma unroll
                    for (int p = 0; p < 16; p++) {
                        fma2(acc[p], wd[p],     wv0);
                        fma2(acc[p], wd[p + 1], wv1);
                        fma2(acc[p], wd[p + 2], wv2);
                    }
                }
            }
        }
    }
    const int nbase = (y0 + r) * WW + x0;
#pragma unroll
    for (int p = 0; p < 16; p++) {
        float2 v = unpk(acc[p]);
        *(float2*)&outp[(nbase + p) * NF + c2] = v;
    }
}

// ---------------------------------------------------------------------------
// Flash attention (R11-exact, measured-best): 256 threads, frag 6x8,
// QROWS=96 -> 134 CTAs, P reuses Bs, float4 P-reads, c-unroll x2.
// ---------------------------------------------------------------------------
#define LD  132
#define LDQ 100
#define QROWS 96
#define SM_Q 0
#define SM_B (128*LDQ)
#define SM_G (128*LDQ + 128*LD)

__global__ __launch_bounds__(256, 1) void flash_kernel()
{
    extern __shared__ float sm[];
    float* Qst = sm + SM_Q;   // [c][i] transposed, i < 96
    float* Bs  = sm + SM_B;   // K-chunk, then reused as P
    float* Gs  = sm + SM_G;

    const int b  = blockIdx.y;
    const int q0 = blockIdx.x * QROWS;
    const float* __restrict__ theta = g_qkv[0][b];
    const float* __restrict__ phi   = g_qkv[1][b];
    const float* __restrict__ gmat  = g_qkv[2][b];

    const int t  = threadIdx.x;
    const int tx = t & 15, ty = t >> 4;
    const int i0 = ty * 6, j0 = tx * 8;

    for (int idx = t; idx < QROWS * 128; idx += 256) {
        int i = idx >> 7, c = idx & 127;
        int qi = q0 + i; if (qi >= NPIX) qi = NPIX - 1;
        Qst[c * LDQ + i] = theta[qi * NF + c];
    }

    ull o2[6][4];
    float mrun[6], lrun[6];
#pragma unroll
    for (int ii = 0; ii < 6; ii++) {
        mrun[ii] = -1e30f; lrun[ii] = 0.f;
#pragma unroll
        for (int cp = 0; cp < 4; cp++) o2[ii][cp] = dup2(0.f);
    }
    __syncthreads();

    for (int km = 0; km < 50; km++) {
        const int m0 = km * 128;
        for (int idx = t; idx < 4096; idx += 256) {
            int rr = idx >> 5;
            int cc = (idx & 31) << 2;
            *(float4*)&Bs[rr * LD + cc] = *(const float4*)&phi[rr * NPIX + m0 + cc];
            *(float4*)&Gs[rr * LD + cc] = *(const float4*)&gmat[(m0 + rr) * NF + cc];
        }
        __syncthreads();

        ull s2[6][4];
#pragma unroll
        for (int ii = 0; ii < 6; ii++)
#pragma unroll
            for (int jp = 0; jp < 4; jp++) s2[ii][jp] = dup2(0.f);

#pragma unroll 1
        for (int c = 0; c < 128; c += 2) {
#pragma unroll
            for (int cc2 = 0; cc2 < 2; cc2++) {
                const float* qrow = &Qst[(c + cc2) * LDQ + i0];
                float2 a01 = *(const float2*)&qrow[0];
                float2 a23 = *(const float2*)&qrow[2];
                float2 a45 = *(const float2*)&qrow[4];
                ull av[6] = {dup2(a01.x), dup2(a01.y), dup2(a23.x),
                             dup2(a23.y), dup2(a45.x), dup2(a45.y)};
                const ulonglong2* brow = (const ulonglong2*)&Bs[(c + cc2) * LD + j0];
                ulonglong2 b01 = brow[0], b23 = brow[1];
                ull bv[4] = {b01.x, b01.y, b23.x, b23.y};
#pragma unroll
                for (int ii = 0; ii < 6; ii++)
#pragma unroll
                    for (int jp = 0; jp < 4; jp++)
                        fma2(s2[ii][jp], av[ii], bv[jp]);
            }
        }
        __syncthreads();

#pragma unroll
        for (int ii = 0; ii < 6; ii++) {
            float sv[8];
            float2 u;
            u = unpk(s2[ii][0]); sv[0] = u.x; sv[1] = u.y;
            u = unpk(s2[ii][1]); sv[2] = u.x; sv[3] = u.y;
            u = unpk(s2[ii][2]); sv[4] = u.x; sv[5] = u.y;
            u = unpk(s2[ii][3]); sv[6] = u.x; sv[7] = u.y;
            float mx = sv[0];
#pragma unroll
            for (int jj = 1; jj < 8; jj++) mx = fmaxf(mx, sv[jj]);
            mx = fmaxf(mx, __shfl_xor_sync(0xffffffffu, mx, 1));
            mx = fmaxf(mx, __shfl_xor_sync(0xffffffffu, mx, 2));
            mx = fmaxf(mx, __shfl_xor_sync(0xffffffffu, mx, 4));
            mx = fmaxf(mx, __shfl_xor_sync(0xffffffffu, mx, 8));
            float mnew = fmaxf(mrun[ii], mx);
            float f = __expf(mrun[ii] - mnew);
            mrun[ii] = mnew;
            float sum = 0.f;
#pragma unroll
            for (int jj = 0; jj < 8; jj++) {
                float p = __expf(sv[jj] - mnew);
                sv[jj] = p;
                sum += p;
            }
            sum += __shfl_xor_sync(0xffffffffu, sum, 1);
            sum += __shfl_xor_sync(0xffffffffu, sum, 2);
            sum += __shfl_xor_sync(0xffffffffu, sum, 4);
            sum += __shfl_xor_sync(0xffffffffu, sum, 8);
            lrun[ii] = lrun[ii] * f + sum;
            ull f2v = dup2(f);
#pragma unroll
            for (int cp = 0; cp < 4; cp++)
                o2[ii][cp] = mul2(o2[ii][cp], f2v);
            *(float4*)&Bs[(i0 + ii) * LD + j0]     = make_float4(sv[0], sv[1], sv[2], sv[3]);
            *(float4*)&Bs[(i0 + ii) * LD + j0 + 4] = make_float4(sv[4], sv[5], sv[6], sv[7]);
        }
        __syncthreads();

#pragma unroll 1
        for (int j4 = 0; j4 < 128; j4 += 4) {
            float4 pv4[6];
#pragma unroll
            for (int ii = 0; ii < 6; ii++)
                pv4[ii] = *(const float4*)&Bs[(i0 + ii) * LD + j4];
#pragma unroll
            for (int jj = 0; jj < 4; jj++) {
                const ulonglong2* grow = (const ulonglong2*)&Gs[(j4 + jj) * LD + j0];
                ulonglong2 g01 = grow[0], g23 = grow[1];
                ull gv[4] = {g01.x, g01.y, g23.x, g23.y};
#pragma unroll
                for (int ii = 0; ii < 6; ii++) {
                    float pj = (jj == 0) ? pv4[ii].x : (jj == 1) ? pv4[ii].y
                             : (jj == 2) ? pv4[ii].z : pv4[ii].w;
                    ull pv = dup2(pj);
#pragma unroll
                    for (int cp = 0; cp < 4; cp++)
                        fma2(o2[ii][cp], pv, gv[cp]);
                }
            }
        }
        __syncthreads();
    }

#pragma unroll
    for (int ii = 0; ii < 6; ii++) {
        int row = q0 + i0 + ii;
        if (row >= NPIX) continue;
        float inv = 1.f / lrun[ii];
        float2 v0 = unpk(o2[ii][0]), v1 = unpk(o2[ii][1]);
        float2 v2 = unpk(o2[ii][2]), v3 = unpk(o2[ii][3]);
        float* dst = &g_att[b][row * NF + j0];
        *(float4*)&dst[0] = make_float4(v0.x * inv, v0.y * inv, v1.x * inv, v1.y * inv);
        *(float4*)&dst[4] = make_float4(v2.x * inv, v2.y * inv, v3.x * inv, v3.y * inv);
    }
}

// ---------------------------------------------------------------------------
// Final conv 3x3, 128 -> 256, + residual add, writes d_out.
// R15-recipe: tile 2 rows x 16 px x 256 co, 256 threads (c2=2*(t&127),
// r=t>>7), 16px x 2co per thread, smem 40KB -> 5 CTAs/SM, grid 400.
// ---------------------------------------------------------------------------
#define PADF 20
__global__ __launch_bounds__(256) void conv_final_kernel(
    const float* __restrict__ x,
    const float* __restrict__ wc,
    float* __restrict__ out)
{
    extern __shared__ float s_in[];            // [4][NF][PADF] (18 used)
    const int x0 = blockIdx.x * 16;
    const int y0 = blockIdx.y * 2;
    const int b  = blockIdx.z;
    const int t  = threadIdx.x;
    const float* __restrict__ ain = g_att[b];

    for (int i = t; i < 4 * 18 * NF; i += 256) {
        int ci = i & (NF - 1);
        int xi = (i >> 7) % 18;
        int r  = i / (18 * NF);
        int gy = y0 - 1 + r, gx = x0 - 1 + xi;
        float v = 0.f;
        if (gy >= 0 && gy < HH && gx >= 0 && gx < WW)
            v = ain[(gy * WW + gx) * NF + ci];
        s_in[(r * NF + ci) * PADF + xi] = v;
    }
    __syncthreads();

    const int c2 = (t & 127) * 2;
    const int r  = t >> 7;    // 0..1

    ull acc[16];
#pragma unroll
    for (int p = 0; p < 16; p++) acc[p] = dup2(0.f);

    const int kstride = NF * CI;   // weight offset per kx

    for (int ky = 0; ky < 3; ky++) {
        const float* srow0 = &s_in[((r + ky) * NF) * PADF];
        const float* wbase = &wc[(ky * 3 * NF) * CI + c2];
        ull a0 = *(const ull*)&wbase[0];
        ull a1 = *(const ull*)&wbase[kstride];
        ull a2 = *(const ull*)&wbase[2 * kstride];
        ull e0 = *(const ull*)&wbase[CI];
        ull e1 = *(const ull*)&wbase[kstride + CI];
        ull e2 = *(const ull*)&wbase[2 * kstride + CI];
#pragma unroll 1
        for (int ci = 0; ci < NF; ci += 2) {
            ull u0 = a0, u1 = a1, u2 = a2;
            ull v0 = e0, v1 = e1, v2 = e2;
            if (ci + 2 < NF) {
                const float* wn = wbase + (ci + 2) * CI;
                a0 = *(const ull*)&wn[0];
                a1 = *(const ull*)&wn[kstride];
                a2 = *(const ull*)&wn[2 * kstride];
                e0 = *(const ull*)&wn[CI];
                e1 = *(const ull*)&wn[kstride + CI];
                e2 = *(const ull*)&wn[2 * kstride + CI];
            }
#pragma unroll
            for (int half = 0; half < 2; half++) {
                const float* row = srow0 + (ci + half) * PADF;
                float4 wA = *(const float4*)&row[0];
                float4 wB = *(const float4*)&row[4];
                float4 wC = *(const float4*)&row[8];
                float4 wD = *(const float4*)&row[12];
                float2 wE = *(const float2*)&row[16];
                ull wd[18];
                wd[0]=dup2(wA.x);  wd[1]=dup2(wA.y);  wd[2]=dup2(wA.z);  wd[3]=dup2(wA.w);
                wd[4]=dup2(wB.x);  wd[5]=dup2(wB.y);  wd[6]=dup2(wB.z);  wd[7]=dup2(wB.w);
                wd[8]=dup2(wC.x);  wd[9]=dup2(wC.y);  wd[10]=dup2(wC.z); wd[11]=dup2(wC.w);
                wd[12]=dup2(wD.x); wd[13]=dup2(wD.y); wd[14]=dup2(wD.z); wd[15]=dup2(wD.w);
                wd[16]=dup2(wE.x); wd[17]=dup2(wE.y);
                ull wv0 = half ? v0 : u0;
                ull wv1 = half ? v1 : u1;
                ull wv2 = half ? v2 : u2;
#pragma unroll
                for (int p = 0; p < 16; p++) {
                    fma2(acc[p], wd[p],     wv0);
                    fma2(acc[p], wd[p + 1], wv1);
                    fma2(acc[p], wd[p + 2], wv2);
                }
            }
        }
    }
#pragma unroll
    for (int p = 0; p < 16; p++) {
        float2 v = unpk(acc[p]);
        int gi = ((b * HH + y0 + r) * WW + x0 + p) * CI + c2;
        float2 xv = *(const float2*)&x[gi];
        *(float2*)&out[gi] = make_float2(xv.x + v.x, xv.y + v.y);
    }
}

// ---------------------------------------------------------------------------
extern "C" void kernel_launch(void* const* d_in, const int* in_sizes, int n_in,
                              void* d_out, int out_size)
{
    const float* x  = (const float*)d_in[0];
    const float* wt = (const float*)d_in[1];
    const float* wp = (const float*)d_in[2];
    const float* wg = (const float*)d_in[3];
    const float* wc = (const float*)d_in[4];
    float* out = (float*)d_out;

    const int smem_qkv   = (QR + 2) * CIH * PADQ * 4;         // 40960
    const int smem_flash = (128 * LDQ + 2 * 128 * LD) * 4;    // 186368
    const int smem_final = 4 * NF * PADF * 4;                 // 40960

    cudaFuncSetAttribute(conv_qkv_kernel,   cudaFuncAttributeMaxDynamicSharedMemorySize, smem_qkv);
    cudaFuncSetAttribute(flash_kernel,      cudaFuncAttributeMaxDynamicSharedMemorySize, smem_flash);
    cudaFuncSetAttribute(conv_final_kernel, cudaFuncAttributeMaxDynamicSharedMemorySize, smem_final);

    const int qtiles = (NPIX + QROWS - 1) / QROWS;            // 67

    conv_qkv_kernel<<<dim3(5, HH / QR, 6), 128, smem_qkv>>>(x, wt, wp, wg);
    flash_kernel<<<dim3(qtiles, 2), 256, smem_flash>>>();
    conv_final_kernel<<<dim3(5, HH / 2, 2), 256, smem_final>>>(x, wc, out);
}